// round 3
// baseline (speedup 1.0000x reference)
#include <cuda_runtime.h>
#include <math.h>

#define VOL   2097152              // 128^3
#define NB    4
#define S2D   16384                // 128*128 (z stride)

// Normalized 1-D Gaussian weights (sigma=1.6, 7 taps), sum = 1.
#define W0 0.25603832f   // center
#define W1 0.21061137f   // +-1
#define W2 0.11722290f   // +-2
#define W3 0.04414655f   // +-3

// Scratch (allocation-free contract: __device__ globals)
__device__ float g_a [(size_t)NB * VOL];   // d   smoothed in x,y
__device__ float g_b [(size_t)NB * VOL];   // |curl v| smoothed in x,y

#define TS  32
#define LD  38   // TS + 2*3   (conv halo)
#define TP  39   // LD + 1     (fdiff needs +1 neighbor)
#define TPS 40   // padded shared stride

// ---------------------------------------------------------------------------
// Kernel 1: FUSED |curl(v)| + separable X,Y Gaussian smoothing -> g_b.
// Stage u,v (planes zz, zz+1) and w (plane z) as 39x39 shared tiles with
// coalesced loads, then compute the 38x38 vn halo entirely from shared.
// fdiff(f,i) = f[min(i,126)+1]-f[min(i,126)]; conv uses zero padding.
// ---------------------------------------------------------------------------
__global__ __launch_bounds__(256)
void curl_smooth_xy_kernel(const float* __restrict__ v) {
    int nz = blockIdx.z;             // n*128 + z
    int n = nz >> 7, z = nz & 127;
    int tx0 = blockIdx.x * TS;
    int ty0 = blockIdx.y * TS;

    const float* pu = v + (size_t)(n * 3 + 0) * VOL;
    const float* pv = v + (size_t)(n * 3 + 1) * VOL;
    const float* pw = v + (size_t)(n * 3 + 2) * VOL;

    __shared__ float s_uA[TP][TPS], s_uB[TP][TPS];
    __shared__ float s_vA[TP][TPS], s_vB[TP][TPS];
    __shared__ float s_w [TP][TPS];
    __shared__ float s_in[LD][TPS];
    __shared__ float s_tmp[LD][TS];

    int tid = threadIdx.x;
    int zz = min(z, 126);
    int offA = zz * S2D, offB = (zz + 1) * S2D, offZ = z * S2D;

    // ---- staged, coalesced loads (coords clamped; out-of-range slots unused)
    for (int l = tid; l < TP * TP; l += 256) {
        int ly = l / TP, lx = l - ly * TP;
        int gy = min(max(ty0 + ly - 3, 0), 127);
        int gx = min(max(tx0 + lx - 3, 0), 127);
        int o = gy * 128 + gx;
        s_uA[ly][lx] = pu[offA + o];
        s_uB[ly][lx] = pu[offB + o];
        s_vA[ly][lx] = pv[offA + o];
        s_vB[ly][lx] = pv[offB + o];
        s_w [ly][lx] = pw[offZ + o];
    }
    __syncthreads();

    // ---- vn halo tile from shared
    const float (*uP)[TPS] = (z <= 126) ? s_uA : s_uB;
    const float (*vP)[TPS] = (z <= 126) ? s_vA : s_vB;

    for (int l = tid; l < LD * LD; l += 256) {
        int ly = l / LD, lx = l - ly * LD;
        int gy = ty0 + ly - 3, gx = tx0 + lx - 3;
        float val = 0.f;
        if ((unsigned)gy < 128u && (unsigned)gx < 128u) {
            int ry = (gy <= 126) ? ly : ly - 1;   // index of min(gy,126)
            int rx = (gx <= 126) ? lx : lx - 1;

            float du_dz = s_uB[ly][lx]   - s_uA[ly][lx];
            float dv_dz = s_vB[ly][lx]   - s_vA[ly][lx];
            float du_dy = uP[ry + 1][lx] - uP[ry][lx];
            float dv_dx = vP[ly][rx + 1] - vP[ly][rx];
            float dw_dy = s_w[ry + 1][lx] - s_w[ry][lx];
            float dw_dx = s_w[ly][rx + 1] - s_w[ly][rx];

            float cu = dw_dy - dv_dz;
            float cv = du_dz - dw_dx;
            float cw = dv_dx - du_dy;
            val = sqrtf(cu * cu + cv * cv + cw * cw);
        }
        s_in[ly][lx] = val;
    }
    __syncthreads();

    // ---- x pass
    for (int l = tid; l < LD * TS; l += 256) {
        int ly = l >> 5, ox = l & 31;
        const float* r = &s_in[ly][ox];
        s_tmp[ly][ox] = W0 * r[3]
                      + W1 * (r[2] + r[4])
                      + W2 * (r[1] + r[5])
                      + W3 * (r[0] + r[6]);
    }
    __syncthreads();

    // ---- y pass + store
    float* out_slice = g_b + (size_t)n * VOL + z * S2D;
    for (int l = tid; l < TS * TS; l += 256) {
        int oy = l >> 5, ox = l & 31;
        float acc = W0 * s_tmp[oy + 3][ox]
                  + W1 * (s_tmp[oy + 2][ox] + s_tmp[oy + 4][ox])
                  + W2 * (s_tmp[oy + 1][ox] + s_tmp[oy + 5][ox])
                  + W3 * (s_tmp[oy + 0][ox] + s_tmp[oy + 6][ox]);
        out_slice[(ty0 + oy) * 128 + tx0 + ox] = acc;
    }
}

// ---------------------------------------------------------------------------
// Kernel 2: separable X+Y Gaussian smoothing of d -> g_a (zero-padded).
// ---------------------------------------------------------------------------
__global__ __launch_bounds__(256)
void smooth_xy_kernel(const float* __restrict__ src) {
    int nz = blockIdx.z;
    int n = nz >> 7, z = nz & 127;
    int tx0 = blockIdx.x * TS;
    int ty0 = blockIdx.y * TS;
    const float* slice = src + (size_t)n * VOL + z * S2D;

    __shared__ float s_in[LD][TPS];
    __shared__ float s_tmp[LD][TS];

    int tid = threadIdx.x;

    for (int l = tid; l < LD * LD; l += 256) {
        int ly = l / LD, lx = l - ly * LD;
        int gy = ty0 + ly - 3, gx = tx0 + lx - 3;
        float val = 0.f;
        if ((unsigned)gy < 128u && (unsigned)gx < 128u)
            val = slice[gy * 128 + gx];
        s_in[ly][lx] = val;
    }
    __syncthreads();

    for (int l = tid; l < LD * TS; l += 256) {
        int ly = l >> 5, ox = l & 31;
        const float* r = &s_in[ly][ox];
        s_tmp[ly][ox] = W0 * r[3]
                      + W1 * (r[2] + r[4])
                      + W2 * (r[1] + r[5])
                      + W3 * (r[0] + r[6]);
    }
    __syncthreads();

    float* out_slice = g_a + (size_t)n * VOL + z * S2D;
    for (int l = tid; l < TS * TS; l += 256) {
        int oy = l >> 5, ox = l & 31;
        float acc = W0 * s_tmp[oy + 3][ox]
                  + W1 * (s_tmp[oy + 2][ox] + s_tmp[oy + 4][ox])
                  + W2 * (s_tmp[oy + 1][ox] + s_tmp[oy + 5][ox])
                  + W3 * (s_tmp[oy + 0][ox] + s_tmp[oy + 6][ox]);
        out_slice[(ty0 + oy) * 128 + tx0 + ox] = acc;
    }
}

// ---------------------------------------------------------------------------
// Kernel 3: fused Z-smooth + flip + cumsum + transform + trapezoid + clip.
// 4 chunks of 32 zf-steps per column. Warp = 32 consecutive columns at one
// chunk -> fully coalesced 128B loads. Cross-chunk scan & reduction via smem.
// Block: 64 columns x 4 chunks = 256 threads.
// ---------------------------------------------------------------------------
__global__ __launch_bounds__(256)
void integrate_kernel(float* __restrict__ out) {
    int chunk = threadIdx.x >> 6;            // 0..3
    int cl    = threadIdx.x & 63;            // 0..63
    int colg  = blockIdx.x * 64 + cl;        // 0..65535
    int n  = colg >> 14;
    int yx = colg & 16383;

    const float* A = g_a + (size_t)n * VOL + yx;  // ds  (xy-smoothed)
    const float* B = g_b + (size_t)n * VOL + yx;  // vn  (xy-smoothed)

    const int z0 = 127 - 32 * chunk;         // first z of this chunk (walk down)

    __shared__ float s_sum[4][64];
    __shared__ float s_iv [4][64];

    // ---------------- Pass 1: local sum of z-smoothed ds over 32 steps ----
    float a[7];
#pragma unroll
    for (int k = 0; k < 7; k++) {
        int zi = z0 + k - 3;
        a[k] = ((unsigned)zi < 128u) ? A[zi * S2D] : 0.f;
    }
    float S = 0.f;
    {
        int z = z0;
#pragma unroll 8
        for (int i = 0; i < 32; i++) {
            float na = 0.f;
            int pz = z - 4;
            if (pz >= 0) na = A[pz * S2D];
            S += W0 * a[3] + W1 * (a[2] + a[4])
               + W2 * (a[1] + a[5]) + W3 * (a[0] + a[6]);
#pragma unroll
            for (int k = 6; k >= 1; k--) a[k] = a[k - 1];
            a[0] = na;
            z--;
        }
    }

    s_sum[chunk][cl] = S;
    __syncthreads();

    float Xoff = 0.f;
#pragma unroll
    for (int c = 0; c < 3; c++)
        if (c < chunk) Xoff += s_sum[c][cl];

    // ---------------- Boundary state for chunk > 0 ------------------------
    float tprev = 0.f, vprev = 0.f;
    if (chunk > 0) {
        int zb = z0 + 1;   // z of zf = 32*chunk - 1; all taps in-bounds
        vprev = W0 * B[zb * S2D]
              + W1 * (B[(zb - 1) * S2D] + B[(zb + 1) * S2D])
              + W2 * (B[(zb - 2) * S2D] + B[(zb + 2) * S2D])
              + W3 * (B[(zb - 3) * S2D] + B[(zb + 3) * S2D]);
        tprev = (Xoff * 20.f + 1.f) * __expf(-20.f * Xoff);
    }

    // ---------------- Pass 2: full evaluation -----------------------------
    float b[7];
#pragma unroll
    for (int k = 0; k < 7; k++) {
        int zi = z0 + k - 3;
        if ((unsigned)zi < 128u) {
            a[k] = A[zi * S2D];
            b[k] = B[zi * S2D];
        } else {
            a[k] = 0.f; b[k] = 0.f;
        }
    }

    float xacc = Xoff, iv = 0.f;
    int z = z0;
#pragma unroll 8
    for (int i = 0; i < 32; i++) {
        float na = 0.f, nb = 0.f;
        int pz = z - 4;
        if (pz >= 0) { na = A[pz * S2D]; nb = B[pz * S2D]; }

        float ds_s = W0 * a[3] + W1 * (a[2] + a[4])
                   + W2 * (a[1] + a[5]) + W3 * (a[0] + a[6]);
        float vn_s = W0 * b[3] + W1 * (b[2] + b[4])
                   + W2 * (b[1] + b[5]) + W3 * (b[0] + b[6]);

        xacc += ds_s;
        float tt = (xacc * 20.f + 1.f) * __expf(-20.f * xacc);

        if (i == 0 && chunk == 0)
            iv = (1.f - tt) * vn_s;                       // front term
        else
            iv += (tprev - tt) * (vprev + vn_s) * 0.5f;   // trapezoid
        tprev = tt; vprev = vn_s;

#pragma unroll
        for (int k = 6; k >= 1; k--) { a[k] = a[k - 1]; b[k] = b[k - 1]; }
        a[0] = na; b[0] = nb;
        z--;
    }

    s_iv[chunk][cl] = iv;
    __syncthreads();

    if (chunk == 0) {
        float tot = iv + s_iv[1][cl] + s_iv[2][cl] + s_iv[3][cl];
        out[colg] = fminf(fmaxf(tot, 0.f), 1.f);
    }
}

// ---------------------------------------------------------------------------
extern "C" void kernel_launch(void* const* d_in, const int* in_sizes, int n_in,
                              void* d_out, int out_size) {
    const float* d = (const float*)d_in[0];
    const float* v = (const float*)d_in[1];
    if (in_sizes[0] > in_sizes[1]) {   // safety: d is the smaller tensor
        const float* tmp = d; d = v; v = tmp;
    }
    float* out = (float*)d_out;

    dim3 g2(128 / TS, 128 / TS, NB * 128);
    curl_smooth_xy_kernel<<<g2, 256>>>(v);   // |curl v| -> smooth xy -> g_b
    smooth_xy_kernel<<<g2, 256>>>(d);        // d -> smooth xy -> g_a

    integrate_kernel<<<65536 / 64, 256>>>(out);
}

// round 4
// speedup vs baseline: 1.3519x; 1.3519x over previous
#include <cuda_runtime.h>
#include <math.h>

#define VOL   2097152              // 128^3
#define NB    4
#define S2D   16384                // 128*128 (z stride)

// Normalized 1-D Gaussian weights (sigma=1.6, 7 taps), sum = 1.
#define W0 0.25603832f   // center
#define W1 0.21061137f   // +-1
#define W2 0.11722290f   // +-2
#define W3 0.04414655f   // +-3

// Scratch (allocation-free contract: __device__ globals)
__device__ float g_a [(size_t)NB * VOL];   // d   smoothed in x,y
__device__ float g_b [(size_t)NB * VOL];   // |curl v| smoothed in x,y

#define TS  32
#define LD  38   // TS + 2*3 (conv halo)
#define SP  40   // padded shared stride

// ---------------------------------------------------------------------------
// Fused kernel: per (n, z, 32x32 tile) block does BOTH
//   phase A: d  -> separable X,Y smooth -> g_a        (DRAM-leaning)
//   phase B: |curl v| -> separable X,Y smooth -> g_b  (L1-leaning)
// Phases share the smem buffers; blocks pipeline the two phases across SMs.
//
// fdiff(f,i) = f[min(i,126)+1]-f[min(i,126)]  is rewritten as
//   diff = e * (f[o + delta] - f[o]),  delta=+s, e=+1   (i < 127)
//   diff = e * (f[o - s]    - f[o]),  e=-1              (i == 127)
// so each field needs ONE base load; 9 LDG per halo point total.
// Convolution uses zero padding outside the 128x128 slice.
// ---------------------------------------------------------------------------
__global__ __launch_bounds__(256)
void fused_smooth_kernel(const float* __restrict__ d,
                         const float* __restrict__ v) {
    int nz = blockIdx.z;             // n*128 + z
    int n = nz >> 7, z = nz & 127;
    int tx0 = blockIdx.x * TS;
    int ty0 = blockIdx.y * TS;

    __shared__ float s_in[LD][SP];
    __shared__ float s_tmp[LD][TS];

    int tid = threadIdx.x;

    // ======================= phase A : smooth(d) =========================
    {
        const float* slice = d + (size_t)n * VOL + z * S2D;
        for (int l = tid; l < LD * LD; l += 256) {
            int ly = l / LD, lx = l - ly * LD;
            int gy = ty0 + ly - 3, gx = tx0 + lx - 3;
            float val = 0.f;
            if ((unsigned)gy < 128u && (unsigned)gx < 128u)
                val = slice[gy * 128 + gx];
            s_in[ly][lx] = val;
        }
    }
    __syncthreads();

    for (int l = tid; l < LD * TS; l += 256) {
        int ly = l >> 5, ox = l & 31;
        const float* r = &s_in[ly][ox];
        s_tmp[ly][ox] = W0 * r[3]
                      + W1 * (r[2] + r[4])
                      + W2 * (r[1] + r[5])
                      + W3 * (r[0] + r[6]);
    }
    __syncthreads();

    {
        float* out_slice = g_a + (size_t)n * VOL + z * S2D;
        for (int l = tid; l < TS * TS; l += 256) {
            int oy = l >> 5, ox = l & 31;
            float acc = W0 * s_tmp[oy + 3][ox]
                      + W1 * (s_tmp[oy + 2][ox] + s_tmp[oy + 4][ox])
                      + W2 * (s_tmp[oy + 1][ox] + s_tmp[oy + 5][ox])
                      + W3 * (s_tmp[oy + 0][ox] + s_tmp[oy + 6][ox]);
            out_slice[(ty0 + oy) * 128 + tx0 + ox] = acc;
        }
    }

    // ======================= phase B : smooth(|curl v|) ==================
    // s_in is free (phase-A x-pass finished before the 2nd sync above);
    // refill it with the vn halo. One sync below also covers the pending
    // s_tmp reads from phase-A's y-pass before we overwrite s_tmp.
    {
        const float* pu = v + (size_t)(n * 3 + 0) * VOL;
        const float* pv = v + (size_t)(n * 3 + 1) * VOL;
        const float* pw = v + (size_t)(n * 3 + 2) * VOL;

        const int   dz = (z < 127) ? S2D : -S2D;   // per-block constants
        const float ez = (z < 127) ? 1.f : -1.f;

        for (int l = tid; l < LD * LD; l += 256) {
            int ly = l / LD, lx = l - ly * LD;
            int gy = ty0 + ly - 3, gx = tx0 + lx - 3;
            float val = 0.f;
            if ((unsigned)gy < 128u && (unsigned)gx < 128u) {
                int   dy = (gy < 127) ? 128 : -128;
                float ey = (gy < 127) ? 1.f : -1.f;
                int   dx = (gx < 127) ? 1 : -1;
                float ex = (gx < 127) ? 1.f : -1.f;

                int o = z * S2D + gy * 128 + gx;

                float uc = pu[o], vc = pv[o], wc = pw[o];
                float du_dz = ez * (pu[o + dz] - uc);
                float dv_dz = ez * (pv[o + dz] - vc);
                float du_dy = ey * (pu[o + dy] - uc);
                float dw_dy = ey * (pw[o + dy] - wc);
                float dv_dx = ex * (pv[o + dx] - vc);
                float dw_dx = ex * (pw[o + dx] - wc);

                float cu = dw_dy - dv_dz;
                float cv = du_dz - dw_dx;
                float cw = dv_dx - du_dy;
                val = sqrtf(cu * cu + cv * cv + cw * cw);
            }
            s_in[ly][lx] = val;
        }
    }
    __syncthreads();

    for (int l = tid; l < LD * TS; l += 256) {
        int ly = l >> 5, ox = l & 31;
        const float* r = &s_in[ly][ox];
        s_tmp[ly][ox] = W0 * r[3]
                      + W1 * (r[2] + r[4])
                      + W2 * (r[1] + r[5])
                      + W3 * (r[0] + r[6]);
    }
    __syncthreads();

    {
        float* out_slice = g_b + (size_t)n * VOL + z * S2D;
        for (int l = tid; l < TS * TS; l += 256) {
            int oy = l >> 5, ox = l & 31;
            float acc = W0 * s_tmp[oy + 3][ox]
                      + W1 * (s_tmp[oy + 2][ox] + s_tmp[oy + 4][ox])
                      + W2 * (s_tmp[oy + 1][ox] + s_tmp[oy + 5][ox])
                      + W3 * (s_tmp[oy + 0][ox] + s_tmp[oy + 6][ox]);
            out_slice[(ty0 + oy) * 128 + tx0 + ox] = acc;
        }
    }
}

// ---------------------------------------------------------------------------
// Integrate kernel: fused Z-smooth + flip + cumsum + transform + trapezoid
// + clip.  4 chunks of 32 zf-steps per column; warp = 32 consecutive columns
// at one chunk (coalesced); cross-chunk scan & reduction via smem.
// Block: 64 columns x 4 chunks = 256 threads.
// ---------------------------------------------------------------------------
__global__ __launch_bounds__(256)
void integrate_kernel(float* __restrict__ out) {
    int chunk = threadIdx.x >> 6;            // 0..3
    int cl    = threadIdx.x & 63;            // 0..63
    int colg  = blockIdx.x * 64 + cl;        // 0..65535
    int n  = colg >> 14;
    int yx = colg & 16383;

    const float* A = g_a + (size_t)n * VOL + yx;  // ds  (xy-smoothed)
    const float* B = g_b + (size_t)n * VOL + yx;  // vn  (xy-smoothed)

    const int z0 = 127 - 32 * chunk;         // first z of this chunk (walk down)

    __shared__ float s_sum[4][64];
    __shared__ float s_iv [4][64];

    // ---------------- Pass 1: local sum of z-smoothed ds over 32 steps ----
    float a[7];
#pragma unroll
    for (int k = 0; k < 7; k++) {
        int zi = z0 + k - 3;
        a[k] = ((unsigned)zi < 128u) ? A[zi * S2D] : 0.f;
    }
    float S = 0.f;
    {
        int z = z0;
#pragma unroll 8
        for (int i = 0; i < 32; i++) {
            float na = 0.f;
            int pz = z - 4;
            if (pz >= 0) na = A[pz * S2D];
            S += W0 * a[3] + W1 * (a[2] + a[4])
               + W2 * (a[1] + a[5]) + W3 * (a[0] + a[6]);
#pragma unroll
            for (int k = 6; k >= 1; k--) a[k] = a[k - 1];
            a[0] = na;
            z--;
        }
    }

    s_sum[chunk][cl] = S;
    __syncthreads();

    float Xoff = 0.f;
#pragma unroll
    for (int c = 0; c < 3; c++)
        if (c < chunk) Xoff += s_sum[c][cl];

    // ---------------- Boundary state for chunk > 0 ------------------------
    float tprev = 0.f, vprev = 0.f;
    if (chunk > 0) {
        int zb = z0 + 1;   // z of zf = 32*chunk - 1; all taps in-bounds
        vprev = W0 * B[zb * S2D]
              + W1 * (B[(zb - 1) * S2D] + B[(zb + 1) * S2D])
              + W2 * (B[(zb - 2) * S2D] + B[(zb + 2) * S2D])
              + W3 * (B[(zb - 3) * S2D] + B[(zb + 3) * S2D]);
        tprev = (Xoff * 20.f + 1.f) * __expf(-20.f * Xoff);
    }

    // ---------------- Pass 2: full evaluation -----------------------------
    float b[7];
#pragma unroll
    for (int k = 0; k < 7; k++) {
        int zi = z0 + k - 3;
        if ((unsigned)zi < 128u) {
            a[k] = A[zi * S2D];
            b[k] = B[zi * S2D];
        } else {
            a[k] = 0.f; b[k] = 0.f;
        }
    }

    float xacc = Xoff, iv = 0.f;
    int z = z0;
#pragma unroll 8
    for (int i = 0; i < 32; i++) {
        float na = 0.f, nb = 0.f;
        int pz = z - 4;
        if (pz >= 0) { na = A[pz * S2D]; nb = B[pz * S2D]; }

        float ds_s = W0 * a[3] + W1 * (a[2] + a[4])
                   + W2 * (a[1] + a[5]) + W3 * (a[0] + a[6]);
        float vn_s = W0 * b[3] + W1 * (b[2] + b[4])
                   + W2 * (b[1] + b[5]) + W3 * (b[0] + b[6]);

        xacc += ds_s;
        float tt = (xacc * 20.f + 1.f) * __expf(-20.f * xacc);

        if (i == 0 && chunk == 0)
            iv = (1.f - tt) * vn_s;                       // front term
        else
            iv += (tprev - tt) * (vprev + vn_s) * 0.5f;   // trapezoid
        tprev = tt; vprev = vn_s;

#pragma unroll
        for (int k = 6; k >= 1; k--) { a[k] = a[k - 1]; b[k] = b[k - 1]; }
        a[0] = na; b[0] = nb;
        z--;
    }

    s_iv[chunk][cl] = iv;
    __syncthreads();

    if (chunk == 0) {
        float tot = iv + s_iv[1][cl] + s_iv[2][cl] + s_iv[3][cl];
        out[colg] = fminf(fmaxf(tot, 0.f), 1.f);
    }
}

// ---------------------------------------------------------------------------
extern "C" void kernel_launch(void* const* d_in, const int* in_sizes, int n_in,
                              void* d_out, int out_size) {
    const float* d = (const float*)d_in[0];
    const float* v = (const float*)d_in[1];
    if (in_sizes[0] > in_sizes[1]) {   // safety: d is the smaller tensor
        const float* tmp = d; d = v; v = tmp;
    }
    float* out = (float*)d_out;

    dim3 g2(128 / TS, 128 / TS, NB * 128);
    fused_smooth_kernel<<<g2, 256>>>(d, v);   // g_a (d) and g_b (|curl v|)

    integrate_kernel<<<65536 / 64, 256>>>(out);
}

// round 5
// speedup vs baseline: 1.4843x; 1.0979x over previous
#include <cuda_runtime.h>
#include <math.h>

#define VOL   2097152              // 128^3
#define NB    4
#define S2D   16384                // 128*128 (z stride)

// Normalized 1-D Gaussian weights (sigma=1.6, 7 taps), sum = 1.
#define W0 0.25603832f   // center
#define W1 0.21061137f   // +-1
#define W2 0.11722290f   // +-2
#define W3 0.04414655f   // +-3

// Scratch (allocation-free contract: __device__ globals)
__device__ float g_a [(size_t)NB * VOL];   // d   smoothed in x,y
__device__ float g_b [(size_t)NB * VOL];   // |curl v| smoothed in x,y

#define TSX 64
#define TSY 32
#define LDX 70   // TSX + 6
#define LDY 38   // TSY + 6
#define SPX 72   // padded stride for s_in

// ---------------------------------------------------------------------------
// Fused kernel: per (n, z, 64x32 tile) block does BOTH
//   phase A: d  -> separable X,Y smooth -> g_a
//   phase B: |curl v| -> separable X,Y smooth -> g_b
// fdiff rewritten as diff = e*(f[o+delta]-f[o]) with (delta,e) flipped at the
// i==127 edge, so each field needs ONE base load; 9 LDG per halo point.
// Convolution uses zero padding outside the 128x128 slice.
// ---------------------------------------------------------------------------
__global__ __launch_bounds__(256)
void fused_smooth_kernel(const float* __restrict__ d,
                         const float* __restrict__ v) {
    int nz = blockIdx.z;             // n*128 + z
    int n = nz >> 7, z = nz & 127;
    int tx0 = blockIdx.x * TSX;
    int ty0 = blockIdx.y * TSY;

    __shared__ float s_in[LDY][SPX];
    __shared__ float s_tmp[LDY][TSX];

    int tid = threadIdx.x;

    // ======================= phase A : smooth(d) =========================
    {
        const float* slice = d + (size_t)n * VOL + z * S2D;
        for (int l = tid; l < LDY * LDX; l += 256) {
            int ly = l / LDX, lx = l - ly * LDX;
            int gy = ty0 + ly - 3, gx = tx0 + lx - 3;
            float val = 0.f;
            if ((unsigned)gy < 128u && (unsigned)gx < 128u)
                val = slice[gy * 128 + gx];
            s_in[ly][lx] = val;
        }
    }
    __syncthreads();

    for (int l = tid; l < LDY * TSX; l += 256) {
        int ly = l >> 6, ox = l & 63;
        const float* r = &s_in[ly][ox];
        s_tmp[ly][ox] = W0 * r[3]
                      + W1 * (r[2] + r[4])
                      + W2 * (r[1] + r[5])
                      + W3 * (r[0] + r[6]);
    }
    __syncthreads();

    {
        float* out_slice = g_a + (size_t)n * VOL + z * S2D;
        for (int l = tid; l < TSY * TSX; l += 256) {
            int oy = l >> 6, ox = l & 63;
            float acc = W0 * s_tmp[oy + 3][ox]
                      + W1 * (s_tmp[oy + 2][ox] + s_tmp[oy + 4][ox])
                      + W2 * (s_tmp[oy + 1][ox] + s_tmp[oy + 5][ox])
                      + W3 * (s_tmp[oy + 0][ox] + s_tmp[oy + 6][ox]);
            out_slice[(ty0 + oy) * 128 + tx0 + ox] = acc;
        }
    }

    // ======================= phase B : smooth(|curl v|) ==================
    {
        const float* pu = v + (size_t)(n * 3 + 0) * VOL;
        const float* pv = v + (size_t)(n * 3 + 1) * VOL;
        const float* pw = v + (size_t)(n * 3 + 2) * VOL;

        const int   dz = (z < 127) ? S2D : -S2D;   // per-block constants
        const float ez = (z < 127) ? 1.f : -1.f;

        for (int l = tid; l < LDY * LDX; l += 256) {
            int ly = l / LDX, lx = l - ly * LDX;
            int gy = ty0 + ly - 3, gx = tx0 + lx - 3;
            float val = 0.f;
            if ((unsigned)gy < 128u && (unsigned)gx < 128u) {
                int   dy = (gy < 127) ? 128 : -128;
                float ey = (gy < 127) ? 1.f : -1.f;
                int   dx = (gx < 127) ? 1 : -1;
                float ex = (gx < 127) ? 1.f : -1.f;

                int o = z * S2D + gy * 128 + gx;

                float uc = pu[o], vc = pv[o], wc = pw[o];
                float du_dz = ez * (pu[o + dz] - uc);
                float dv_dz = ez * (pv[o + dz] - vc);
                float du_dy = ey * (pu[o + dy] - uc);
                float dw_dy = ey * (pw[o + dy] - wc);
                float dv_dx = ex * (pv[o + dx] - vc);
                float dw_dx = ex * (pw[o + dx] - wc);

                float cu = dw_dy - dv_dz;
                float cv = du_dz - dw_dx;
                float cw = dv_dx - du_dy;
                val = sqrtf(cu * cu + cv * cv + cw * cw);
            }
            s_in[ly][lx] = val;
        }
    }
    __syncthreads();

    for (int l = tid; l < LDY * TSX; l += 256) {
        int ly = l >> 6, ox = l & 63;
        const float* r = &s_in[ly][ox];
        s_tmp[ly][ox] = W0 * r[3]
                      + W1 * (r[2] + r[4])
                      + W2 * (r[1] + r[5])
                      + W3 * (r[0] + r[6]);
    }
    __syncthreads();

    {
        float* out_slice = g_b + (size_t)n * VOL + z * S2D;
        for (int l = tid; l < TSY * TSX; l += 256) {
            int oy = l >> 6, ox = l & 63;
            float acc = W0 * s_tmp[oy + 3][ox]
                      + W1 * (s_tmp[oy + 2][ox] + s_tmp[oy + 4][ox])
                      + W2 * (s_tmp[oy + 1][ox] + s_tmp[oy + 5][ox])
                      + W3 * (s_tmp[oy + 0][ox] + s_tmp[oy + 6][ox]);
            out_slice[(ty0 + oy) * 128 + tx0 + ox] = acc;
        }
    }
}

// ---------------------------------------------------------------------------
// Integrate kernel: fused Z-smooth + flip + cumsum + transform + trapezoid
// + clip, with SHARED-MEMORY STAGING.
// Block = 32 columns x 8 chunks (16 zf-steps each) = 256 threads.
// Phase 0: coalesced float4 load of the full 128-z extent of A,B for the
//          32 columns into smem (each element read from global exactly once).
// Phase 1: per-chunk smoothed-ds sums (from smem) -> cross-chunk scan.
// Phase 2: full evaluation (from smem) -> cross-chunk reduction.
// ---------------------------------------------------------------------------
__global__ __launch_bounds__(256)
void integrate_kernel(float* __restrict__ out) {
    __shared__ float sA[128][32];
    __shared__ float sB[128][32];
    __shared__ float s_sum[8][32];
    __shared__ float s_iv [8][32];

    int tid   = threadIdx.x;
    int cl    = tid & 31;                    // column within block
    int chunk = tid >> 5;                    // 0..7 (one warp per chunk)

    int colg0 = blockIdx.x * 32;
    int n   = colg0 >> 14;
    int yx0 = colg0 & 16383;                 // 16384 % 32 == 0: no n straddle

    const float* Abase = g_a + (size_t)n * VOL + yx0;
    const float* Bbase = g_b + (size_t)n * VOL + yx0;

    // ---------------- Phase 0: stage columns ------------------------------
    for (int i = tid; i < 128 * 8; i += 256) {      // 8 float4 per z-row
        int z = i >> 3, c4 = (i & 7) << 2;
        *(float4*)&sA[z][c4] = *(const float4*)(Abase + z * S2D + c4);
        *(float4*)&sB[z][c4] = *(const float4*)(Bbase + z * S2D + c4);
    }
    __syncthreads();

    const int z0 = 127 - 16 * chunk;         // first z of this chunk (walk down)

    // ---------------- Phase 1: chunk-local sum of smoothed ds -------------
    float a[7];
#pragma unroll
    for (int k = 0; k < 7; k++) {
        int zi = z0 + k - 3;
        a[k] = ((unsigned)zi < 128u) ? sA[zi][cl] : 0.f;
    }
    float S = 0.f;
    {
        int z = z0;
#pragma unroll
        for (int i = 0; i < 16; i++) {
            int pz = z - 4;
            float na = (pz >= 0) ? sA[pz][cl] : 0.f;
            S += W0 * a[3] + W1 * (a[2] + a[4])
               + W2 * (a[1] + a[5]) + W3 * (a[0] + a[6]);
#pragma unroll
            for (int k = 6; k >= 1; k--) a[k] = a[k - 1];
            a[0] = na;
            z--;
        }
    }
    s_sum[chunk][cl] = S;
    __syncthreads();

    float Xoff = 0.f;
#pragma unroll
    for (int c = 0; c < 7; c++)
        if (c < chunk) Xoff += s_sum[c][cl];

    // ---------------- Boundary state for chunk > 0 ------------------------
    float tprev = 0.f, vprev = 0.f;
    if (chunk > 0) {
        int zb = z0 + 1;   // z at zf = 16*chunk - 1; taps all in [0,127]
        vprev = W0 * sB[zb][cl]
              + W1 * (sB[zb - 1][cl] + sB[zb + 1][cl])
              + W2 * (sB[zb - 2][cl] + sB[zb + 2][cl])
              + W3 * (sB[zb - 3][cl] + sB[zb + 3][cl]);
        tprev = (Xoff * 20.f + 1.f) * __expf(-20.f * Xoff);
    }

    // ---------------- Phase 2: full evaluation ----------------------------
    float b[7];
#pragma unroll
    for (int k = 0; k < 7; k++) {
        int zi = z0 + k - 3;
        if ((unsigned)zi < 128u) {
            a[k] = sA[zi][cl];
            b[k] = sB[zi][cl];
        } else {
            a[k] = 0.f; b[k] = 0.f;
        }
    }

    float xacc = Xoff, iv = 0.f;
    int z = z0;
#pragma unroll
    for (int i = 0; i < 16; i++) {
        int pz = z - 4;
        float na = 0.f, nb = 0.f;
        if (pz >= 0) { na = sA[pz][cl]; nb = sB[pz][cl]; }

        float ds_s = W0 * a[3] + W1 * (a[2] + a[4])
                   + W2 * (a[1] + a[5]) + W3 * (a[0] + a[6]);
        float vn_s = W0 * b[3] + W1 * (b[2] + b[4])
                   + W2 * (b[1] + b[5]) + W3 * (b[0] + b[6]);

        xacc += ds_s;
        float tt = (xacc * 20.f + 1.f) * __expf(-20.f * xacc);

        if (i == 0 && chunk == 0)
            iv = (1.f - tt) * vn_s;                       // front term
        else
            iv += (tprev - tt) * (vprev + vn_s) * 0.5f;   // trapezoid
        tprev = tt; vprev = vn_s;

#pragma unroll
        for (int k = 6; k >= 1; k--) { a[k] = a[k - 1]; b[k] = b[k - 1]; }
        a[0] = na; b[0] = nb;
        z--;
    }

    s_iv[chunk][cl] = iv;
    __syncthreads();

    if (chunk == 0) {
        float tot = iv;
#pragma unroll
        for (int c = 1; c < 8; c++) tot += s_iv[c][cl];
        out[colg0 + cl] = fminf(fmaxf(tot, 0.f), 1.f);
    }
}

// ---------------------------------------------------------------------------
extern "C" void kernel_launch(void* const* d_in, const int* in_sizes, int n_in,
                              void* d_out, int out_size) {
    const float* d = (const float*)d_in[0];
    const float* v = (const float*)d_in[1];
    if (in_sizes[0] > in_sizes[1]) {   // safety: d is the smaller tensor
        const float* tmp = d; d = v; v = tmp;
    }
    float* out = (float*)d_out;

    dim3 g2(128 / TSX, 128 / TSY, NB * 128);
    fused_smooth_kernel<<<g2, 256>>>(d, v);   // g_a (d) and g_b (|curl v|)

    integrate_kernel<<<65536 / 32, 256>>>(out);
}